// round 1
// baseline (speedup 1.0000x reference)
#include <cuda_runtime.h>

#define N_ATOMS   131072
#define N_EDGES   1048576
#define DSTATE    64
#define N_MOLS    4096
#define ETILE     128
#define N_ETILES  (N_EDGES / ETILE)   // 8192
#define ATILE     128
#define N_ATILES  (N_ATOMS / ATILE)   // 1024

// 32 MB scratch for aggregated messages (float4-aligned for red.v4)
__device__ float4 g_new_states4[N_ATOMS * DSTATE / 4];

__device__ __forceinline__ unsigned rna_u(float x) {
    unsigned u; asm("cvt.rna.tf32.f32 %0, %1;" : "=r"(u) : "f"(x)); return u;
}
__device__ __forceinline__ float rna_f(float x) { return __uint_as_float(rna_u(x)); }

__device__ __forceinline__ void mma8(float* c, const unsigned* a, const unsigned* b) {
    asm volatile(
        "mma.sync.aligned.m16n8k8.row.col.f32.tf32.tf32.f32 "
        "{%0,%1,%2,%3}, {%4,%5,%6,%7}, {%8,%9}, {%0,%1,%2,%3};"
        : "+f"(c[0]), "+f"(c[1]), "+f"(c[2]), "+f"(c[3])
        : "r"(a[0]), "r"(a[1]), "r"(a[2]), "r"(a[3]), "r"(b[0]), "r"(b[1]));
}

// One MLP layer for a 128-row tile. 8 warps, warp w owns rows [16w, 16w+16).
// A in smem [128 x ASTRIDE] (tf32-rounded). Wt in smem, [N x WSTRIDE], i.e.
// W transposed (tf32-rounded). Output relu(A@W + bias) -> Ys [128 x YSTRIDE].
template<int KDIM, int NT, int ASTRIDE, int WSTRIDE, int YSTRIDE, bool ROUND>
__device__ __forceinline__ void mlp_layer(
    const float* __restrict__ As, const float* __restrict__ Wt,
    const float* __restrict__ bias, float* __restrict__ Ys,
    int warp, int g, int t)
{
    float c[NT][4];
#pragma unroll
    for (int nt = 0; nt < NT; nt++) {
        float b0 = bias[nt * 8 + 2 * t];
        float b1 = bias[nt * 8 + 2 * t + 1];
        c[nt][0] = b0; c[nt][1] = b1; c[nt][2] = b0; c[nt][3] = b1;
    }
    const unsigned* Au = (const unsigned*)As;
    const unsigned* Wu = (const unsigned*)Wt;
    const int row0 = warp * 16 + g;
#pragma unroll
    for (int kt = 0; kt < KDIM / 8; kt++) {
        const int kb = kt * 8;
        unsigned a[4];
        a[0] = Au[(size_t)row0       * ASTRIDE + kb + t];
        a[1] = Au[(size_t)(row0 + 8) * ASTRIDE + kb + t];
        a[2] = Au[(size_t)row0       * ASTRIDE + kb + t + 4];
        a[3] = Au[(size_t)(row0 + 8) * ASTRIDE + kb + t + 4];
#pragma unroll
        for (int nt = 0; nt < NT; nt++) {
            unsigned b[2];
            b[0] = Wu[(nt * 8 + g) * WSTRIDE + kb + t];
            b[1] = Wu[(nt * 8 + g) * WSTRIDE + kb + t + 4];
            mma8(c[nt], a, b);
        }
    }
#pragma unroll
    for (int nt = 0; nt < NT; nt++) {
        const int col = nt * 8 + 2 * t;
        float v0 = fmaxf(c[nt][0], 0.f), v1 = fmaxf(c[nt][1], 0.f);
        float v2 = fmaxf(c[nt][2], 0.f), v3 = fmaxf(c[nt][3], 0.f);
        if (ROUND) { v0 = rna_f(v0); v1 = rna_f(v1); v2 = rna_f(v2); v3 = rna_f(v3); }
        Ys[(size_t)row0       * YSTRIDE + col]     = v0;
        Ys[(size_t)row0       * YSTRIDE + col + 1] = v1;
        Ys[(size_t)(row0 + 8) * YSTRIDE + col]     = v2;
        Ys[(size_t)(row0 + 8) * YSTRIDE + col + 1] = v3;
    }
}

// SMEM layout (floats) for edge kernel
#define E_XS    0                       // 128*132 (also reused for Y2)
#define E_Y0    (E_XS + 128*132)        // 128*68
#define E_Y1    (E_Y0 + 128*68)         // 128*68
#define E_W0T   (E_Y1 + 128*68)         // 64*132
#define E_W1T   (E_W0T + 64*132)        // 64*68
#define E_W2T   (E_W1T + 64*68)         // 64*68
#define E_B0    (E_W2T + 64*68)         // 64
#define E_B1    (E_B0 + 64)
#define E_B2    (E_B1 + 64)
#define E_IDX   (E_B2 + 64)             // 256 ints (dst[128], src[128])
#define E_SMEM_FLOATS (E_IDX + 256)
#define E_SMEM_BYTES  (E_SMEM_FLOATS * 4)

__global__ void __launch_bounds__(256, 1) zero_kernel() {
    const size_t stride = (size_t)gridDim.x * blockDim.x;
    size_t i = (size_t)blockIdx.x * blockDim.x + threadIdx.x;
    const float4 z = make_float4(0.f, 0.f, 0.f, 0.f);
    for (; i < (size_t)N_ATOMS * DSTATE / 4; i += stride) g_new_states4[i] = z;
}

__global__ void __launch_bounds__(256, 1) edge_kernel(
    const float* __restrict__ atom_states,
    const int* __restrict__ edge_src,
    const int* __restrict__ edge_dst,
    const float* __restrict__ w0, const float* __restrict__ b0,
    const float* __restrict__ w1, const float* __restrict__ b1,
    const float* __restrict__ w2, const float* __restrict__ b2)
{
    extern __shared__ float sm[];
    float* Xs  = sm + E_XS;
    float* Y0  = sm + E_Y0;
    float* Y1  = sm + E_Y1;
    float* W0t = sm + E_W0T;
    float* W1t = sm + E_W1T;
    float* W2t = sm + E_W2T;
    float* bs0 = sm + E_B0;
    float* bs1 = sm + E_B1;
    float* bs2 = sm + E_B2;
    int*   sdst = (int*)(sm + E_IDX);
    int*   ssrc = sdst + 128;

    const int tid  = threadIdx.x;
    const int warp = tid >> 5, lane = tid & 31;
    const int g = lane >> 2, t = lane & 3;

    // Load weights once per CTA: transpose to [N][K] layout, tf32-rounded.
    for (int i = tid; i < 128 * 64; i += 256) {
        int k = i >> 6, n = i & 63;
        W0t[n * 132 + k] = rna_f(w0[i]);
    }
    for (int i = tid; i < 64 * 64; i += 256) {
        int k = i >> 6, n = i & 63;
        W1t[n * 68 + k] = rna_f(w1[i]);
        W2t[n * 68 + k] = rna_f(w2[i]);
    }
    if (tid < 64) { bs0[tid] = b0[tid]; bs1[tid] = b1[tid]; bs2[tid] = b2[tid]; }
    __syncthreads();

    float* g_new = (float*)g_new_states4;

    for (int tile = blockIdx.x; tile < N_ETILES; tile += gridDim.x) {
        const int ebase = tile * ETILE;
        if (tid < 128)       sdst[tid]       = edge_dst[ebase + tid];
        else                 ssrc[tid - 128] = edge_src[ebase + tid - 128];
        __syncthreads();

        // Gather: X[r][0:64] = states[dst], X[r][64:128] = states[src]
        for (int i = tid; i < 128 * 32; i += 256) {
            const int r = i >> 5, q = i & 31;
            const int atom = (q < 16) ? sdst[r] : ssrc[r];
            const float4 v = *(const float4*)(atom_states + (size_t)atom * 64 + (q & 15) * 4);
            float4 o;
            o.x = rna_f(v.x); o.y = rna_f(v.y); o.z = rna_f(v.z); o.w = rna_f(v.w);
            *(float4*)(Xs + (size_t)r * 132 + q * 4) = o;
        }
        __syncthreads();

        mlp_layer<128, 8, 132, 132, 68, true >(Xs, W0t, bs0, Y0, warp, g, t);
        __syncthreads();
        mlp_layer<64,  8, 68,  68,  68, true >(Y0, W1t, bs1, Y1, warp, g, t);
        __syncthreads();
        // Final messages (unrounded fp32) written into Xs region (X is dead).
        mlp_layer<64,  8, 68,  68,  68, false>(Y1, W2t, bs2, Xs, warp, g, t);
        __syncthreads();

        // Scatter: red.add.v4 into g_new_states[dst]
        for (int i = tid; i < 128 * 16; i += 256) {
            const int r = i >> 4, q = i & 15;
            const float4 v = *(const float4*)(Xs + (size_t)r * 68 + q * 4);
            float* p = g_new + (size_t)sdst[r] * 64 + q * 4;
            asm volatile("red.global.add.v4.f32 [%0], {%1,%2,%3,%4};"
                         :: "l"(p), "f"(v.x), "f"(v.y), "f"(v.z), "f"(v.w) : "memory");
        }
        __syncthreads();
    }
}

// SMEM layout (floats) for readout kernel
#define R_XS    0                       // 128*68
#define R_Y0    (R_XS + 128*68)
#define R_Y1    (R_Y0 + 128*68)
#define R_W1T   (R_Y1 + 128*68)         // 64*68
#define R_W2T   (R_W1T + 64*68)         // 64*68
#define R_W3T   (R_W2T + 64*68)         // 16*68
#define R_B1    (R_W3T + 16*68)         // 64
#define R_B2    (R_B1 + 64)             // 64
#define R_B3    (R_B2 + 64)             // 16
#define R_O     (R_B3 + 16)             // 128*16
#define R_SMEM_FLOATS (R_O + 128*16)
#define R_SMEM_BYTES  (R_SMEM_FLOATS * 4)

__global__ void __launch_bounds__(256, 1) readout_kernel(
    const float* __restrict__ fc1w, const float* __restrict__ fc1b,
    const float* __restrict__ fc2w, const float* __restrict__ fc2b,
    const float* __restrict__ outw, const float* __restrict__ outb,
    float* __restrict__ out)
{
    extern __shared__ float sm[];
    float* Xs  = sm + R_XS;
    float* Y0  = sm + R_Y0;
    float* Y1  = sm + R_Y1;
    float* W1t = sm + R_W1T;
    float* W2t = sm + R_W2T;
    float* W3t = sm + R_W3T;
    float* bs1 = sm + R_B1;
    float* bs2 = sm + R_B2;
    float* bs3 = sm + R_B3;
    float* O   = sm + R_O;

    const int tid  = threadIdx.x;
    const int warp = tid >> 5, lane = tid & 31;
    const int g = lane >> 2, t = lane & 3;

    for (int i = tid; i < 64 * 64; i += 256) {
        int k = i >> 6, n = i & 63;
        W1t[n * 68 + k] = rna_f(fc1w[i]);
        W2t[n * 68 + k] = rna_f(fc2w[i]);
    }
    for (int i = tid; i < 64 * 16; i += 256) {
        int k = i >> 4, n = i & 15;
        W3t[n * 68 + k] = rna_f(outw[i]);
    }
    if (tid < 64) { bs1[tid] = fc1b[tid]; bs2[tid] = fc2b[tid]; }
    if (tid < 16) bs3[tid] = outb[tid];
    __syncthreads();

    const int tile = blockIdx.x;
    const float* g_new = (const float*)g_new_states4;

    // Load aggregated states (coalesced), tf32-round
    for (int i = tid; i < 128 * 16; i += 256) {
        const int r = i >> 4, q = i & 15;
        const float4 v = *(const float4*)(g_new + ((size_t)tile * 128 + r) * 64 + q * 4);
        float4 o;
        o.x = rna_f(v.x); o.y = rna_f(v.y); o.z = rna_f(v.z); o.w = rna_f(v.w);
        *(float4*)(Xs + (size_t)r * 68 + q * 4) = o;
    }
    __syncthreads();

    mlp_layer<64, 8, 68, 68, 68, true >(Xs, W1t, bs1, Y0, warp, g, t);
    __syncthreads();
    mlp_layer<64, 8, 68, 68, 68, true >(Y0, W2t, bs2, Y1, warp, g, t);
    __syncthreads();
    mlp_layer<64, 2, 68, 68, 16, false>(Y1, W3t, bs3, O, warp, g, t);
    __syncthreads();

    // Molecule reduction: 128-atom tile = exactly 4 molecules of 32 atoms
    if (tid < 64) {
        const int mol = tid >> 4, col = tid & 15;
        float s = 0.f;
#pragma unroll
        for (int r = 0; r < 32; r++) s += O[(mol * 32 + r) * 16 + col];
        out[((size_t)tile * 4 + mol) * 16 + col] = s;
    }
}

extern "C" void kernel_launch(void* const* d_in, const int* in_sizes, int n_in,
                              void* d_out, int out_size) {
    const float* atom_states = (const float*)d_in[0];
    const int*   edge_src    = (const int*)d_in[1];
    const int*   edge_dst    = (const int*)d_in[2];
    // d_in[3] = atom_seg (structure i/32 is fixed; unused)
    const float* ms0w = (const float*)d_in[4];  const float* ms0b = (const float*)d_in[5];
    const float* ms1w = (const float*)d_in[6];  const float* ms1b = (const float*)d_in[7];
    const float* ms2w = (const float*)d_in[8];  const float* ms2b = (const float*)d_in[9];
    const float* fc1w = (const float*)d_in[10]; const float* fc1b = (const float*)d_in[11];
    const float* fc2w = (const float*)d_in[12]; const float* fc2b = (const float*)d_in[13];
    const float* outw = (const float*)d_in[14]; const float* outb = (const float*)d_in[15];
    float* out = (float*)d_out;

    cudaFuncSetAttribute(edge_kernel, cudaFuncAttributeMaxDynamicSharedMemorySize, E_SMEM_BYTES);
    cudaFuncSetAttribute(readout_kernel, cudaFuncAttributeMaxDynamicSharedMemorySize, R_SMEM_BYTES);

    int sms = 148;
    cudaDeviceGetAttribute(&sms, cudaDevAttrMultiProcessorCount, 0);

    zero_kernel<<<2048, 256>>>();
    edge_kernel<<<sms, 256, E_SMEM_BYTES>>>(atom_states, edge_src, edge_dst,
                                            ms0w, ms0b, ms1w, ms1b, ms2w, ms2b);
    readout_kernel<<<N_ATILES, 256, R_SMEM_BYTES>>>(fc1w, fc1b, fc2w, fc2b,
                                                    outw, outb, out);
}

// round 3
// speedup vs baseline: 1.4284x; 1.4284x over previous
#include <cuda_runtime.h>
#include <cstdint>

#define N_ATOMS   131072
#define N_EDGES   1048576
#define DSTATE    64
#define N_MOLS    4096
#define ETILE     128
#define N_ETILES  (N_EDGES / ETILE)   // 8192
#define N_ATILES  (N_ATOMS / 128)     // 1024

// Scratch: aggregated messages (32MB) + per-atom partial L0 products P,Q (64MB)
__device__ float4 g_new_states4[N_ATOMS * DSTATE / 4];
__device__ float4 g_P4[N_ATOMS * DSTATE / 4];
__device__ float4 g_Q4[N_ATOMS * DSTATE / 4];

__device__ __forceinline__ unsigned rna_u(float x) {
    unsigned u; asm("cvt.rna.tf32.f32 %0, %1;" : "=r"(u) : "f"(x)); return u;
}
__device__ __forceinline__ float rna_f(float x) { return __uint_as_float(rna_u(x)); }

__device__ __forceinline__ void mma8(float* c, const unsigned* a, const unsigned* b) {
    asm volatile(
        "mma.sync.aligned.m16n8k8.row.col.f32.tf32.tf32.f32 "
        "{%0,%1,%2,%3}, {%4,%5,%6,%7}, {%8,%9}, {%0,%1,%2,%3};"
        : "+f"(c[0]), "+f"(c[1]), "+f"(c[2]), "+f"(c[3])
        : "r"(a[0]), "r"(a[1]), "r"(a[2]), "r"(a[3]), "r"(b[0]), "r"(b[1]));
}

// ====================== P/Q precompute kernel ======================
// Per 128-atom tile: X = rna(states); P = X @ W0top; Q = X @ W0bot (no bias/relu).
// Warp w computes rows [16w,16w+16) x all 64 cols. Direct float2 global stores
// (each 4-lane group fills one 32B sector). Also zeroes g_new for this tile.

#define PQ_XS   0                 // 128*68
#define PQ_WT   (PQ_XS + 128*68)  // 64*68 (W0top transposed)
#define PQ_WB   (PQ_WT + 64*68)   // 64*68
#define PQ_SMEM_FLOATS (PQ_WB + 64*68)
#define PQ_SMEM_BYTES  (PQ_SMEM_FLOATS * 4)

__device__ __forceinline__ void pq_layer(
    const float* __restrict__ As, const float* __restrict__ Wt,
    float* __restrict__ gOut, int warp, int g, int t)
{
    float c[8][4];
#pragma unroll
    for (int nt = 0; nt < 8; nt++)
        c[nt][0] = c[nt][1] = c[nt][2] = c[nt][3] = 0.f;
    const unsigned* Au = (const unsigned*)As;
    const unsigned* Wu = (const unsigned*)Wt;
    const int row0 = warp * 16 + g;
#pragma unroll
    for (int kt = 0; kt < 8; kt++) {
        const int kb = kt * 8;
        unsigned a[4];
        a[0] = Au[(row0)     * 68 + kb + t];
        a[1] = Au[(row0 + 8) * 68 + kb + t];
        a[2] = Au[(row0)     * 68 + kb + t + 4];
        a[3] = Au[(row0 + 8) * 68 + kb + t + 4];
#pragma unroll
        for (int nt = 0; nt < 8; nt++) {
            unsigned b[2];
            b[0] = Wu[(nt * 8 + g) * 68 + kb + t];
            b[1] = Wu[(nt * 8 + g) * 68 + kb + t + 4];
            mma8(c[nt], a, b);
        }
    }
#pragma unroll
    for (int nt = 0; nt < 8; nt++) {
        const int col = nt * 8 + 2 * t;
        *(float2*)(gOut + (size_t)(row0)     * 64 + col) = make_float2(c[nt][0], c[nt][1]);
        *(float2*)(gOut + (size_t)(row0 + 8) * 64 + col) = make_float2(c[nt][2], c[nt][3]);
    }
}

__global__ void __launch_bounds__(256, 1) pq_kernel(
    const float* __restrict__ atom_states,
    const float* __restrict__ w0)
{
    extern __shared__ float sm[];
    float* Xs = sm + PQ_XS;
    float* Wt = sm + PQ_WT;
    float* Wb = sm + PQ_WB;

    const int tid  = threadIdx.x;
    const int warp = tid >> 5, lane = tid & 31;
    const int g = lane >> 2, t = lane & 3;
    const int tile = blockIdx.x;

    // w0 row-major [128 (=2D)][64]; rows 0..63 -> dst half (P), 64..127 -> src half (Q)
    for (int i = tid; i < 64 * 64; i += 256) {
        int k = i >> 6, n = i & 63;
        Wt[n * 68 + k] = rna_f(w0[k * 64 + n]);
        Wb[n * 68 + k] = rna_f(w0[(k + 64) * 64 + n]);
    }
    // states tile -> Xs (rna)
    for (int i = tid; i < 128 * 16; i += 256) {
        const int r = i >> 4, q = i & 15;
        const float4 v = *(const float4*)((const float*)0 + 0, atom_states + ((size_t)tile * 128 + r) * 64 + q * 4);
        float4 o;
        o.x = rna_f(v.x); o.y = rna_f(v.y); o.z = rna_f(v.z); o.w = rna_f(v.w);
        *(float4*)(Xs + (size_t)r * 68 + q * 4) = o;
    }
    __syncthreads();

    float* gP = (float*)g_P4 + (size_t)tile * 128 * 64;
    float* gQ = (float*)g_Q4 + (size_t)tile * 128 * 64;
    pq_layer(Xs, Wt, gP, warp, g, t);
    pq_layer(Xs, Wb, gQ, warp, g, t);

    // zero the message-accumulator rows for this tile
    float4* gz = g_new_states4 + (size_t)tile * 128 * 16;
    const float4 z = make_float4(0.f, 0.f, 0.f, 0.f);
    for (int i = tid; i < 128 * 16; i += 256) gz[i] = z;
}

// ====================== edge kernel ======================
// Per 128-edge tile: A0 = rna(relu(P[dst] + Q[src] + b0)); L1, L2 via 32x32
// warp tiles (4 row-groups x 2 col-groups); scatter messages with red.add.v4.

#define E_XS    0                   // 128*68 (A0; reused as L2 output)
#define E_YS    (E_XS + 128*68)     // 128*68 (L1 output)
#define E_W1T   (E_YS + 128*68)     // 64*68
#define E_W2T   (E_W1T + 64*68)     // 64*68
#define E_B0    (E_W2T + 64*68)
#define E_B1    (E_B0 + 64)
#define E_B2    (E_B1 + 64)
#define E_IDX   (E_B2 + 64)         // 256 ints
#define E_SMEM_FLOATS (E_IDX + 256)
#define E_SMEM_BYTES  (E_SMEM_FLOATS * 4)

// warp tile: rows [32*rowg, +32) (two m16 groups), cols [32*colg, +32) (4 x n8)
template<bool ROUND>
__device__ __forceinline__ void layer32(
    const float* __restrict__ As, const float* __restrict__ Wt,
    const float* __restrict__ bias, float* __restrict__ Ys,
    int rowg, int colg, int g, int t)
{
    float c[2][4][4];
#pragma unroll
    for (int nt = 0; nt < 4; nt++) {
        const int col = colg * 32 + nt * 8 + 2 * t;
        float b0 = bias[col], b1 = bias[col + 1];
        c[0][nt][0] = b0; c[0][nt][1] = b1; c[0][nt][2] = b0; c[0][nt][3] = b1;
        c[1][nt][0] = b0; c[1][nt][1] = b1; c[1][nt][2] = b0; c[1][nt][3] = b1;
    }
    const unsigned* Au = (const unsigned*)As;
    const unsigned* Wu = (const unsigned*)Wt;
    const int r0 = rowg * 32 + g;
#pragma unroll
    for (int kt = 0; kt < 8; kt++) {
        const int kb = kt * 8;
        unsigned a[2][4];
#pragma unroll
        for (int rh = 0; rh < 2; rh++) {
            const int rr = r0 + rh * 16;
            a[rh][0] = Au[(rr)      * 68 + kb + t];
            a[rh][1] = Au[(rr + 8)  * 68 + kb + t];
            a[rh][2] = Au[(rr)      * 68 + kb + t + 4];
            a[rh][3] = Au[(rr + 8)  * 68 + kb + t + 4];
        }
#pragma unroll
        for (int nt = 0; nt < 4; nt++) {
            unsigned b[2];
            b[0] = Wu[(colg * 32 + nt * 8 + g) * 68 + kb + t];
            b[1] = Wu[(colg * 32 + nt * 8 + g) * 68 + kb + t + 4];
            mma8(c[0][nt], a[0], b);
            mma8(c[1][nt], a[1], b);
        }
    }
#pragma unroll
    for (int rh = 0; rh < 2; rh++) {
        const int rr = r0 + rh * 16;
#pragma unroll
        for (int nt = 0; nt < 4; nt++) {
            const int col = colg * 32 + nt * 8 + 2 * t;
            float v0 = fmaxf(c[rh][nt][0], 0.f), v1 = fmaxf(c[rh][nt][1], 0.f);
            float v2 = fmaxf(c[rh][nt][2], 0.f), v3 = fmaxf(c[rh][nt][3], 0.f);
            if (ROUND) { v0 = rna_f(v0); v1 = rna_f(v1); v2 = rna_f(v2); v3 = rna_f(v3); }
            Ys[(rr)     * 68 + col]     = v0;
            Ys[(rr)     * 68 + col + 1] = v1;
            Ys[(rr + 8) * 68 + col]     = v2;
            Ys[(rr + 8) * 68 + col + 1] = v3;
        }
    }
}

__global__ void __launch_bounds__(256, 2) edge_kernel(
    const int* __restrict__ edge_src,
    const int* __restrict__ edge_dst,
    const float* __restrict__ b0,
    const float* __restrict__ w1, const float* __restrict__ b1,
    const float* __restrict__ w2, const float* __restrict__ b2)
{
    extern __shared__ float sm[];
    float* Xs  = sm + E_XS;
    float* Ys  = sm + E_YS;
    float* W1t = sm + E_W1T;
    float* W2t = sm + E_W2T;
    float* bs0 = sm + E_B0;
    float* bs1 = sm + E_B1;
    float* bs2 = sm + E_B2;
    int*   sdst = (int*)(sm + E_IDX);
    int*   ssrc = sdst + 128;

    const int tid  = threadIdx.x;
    const int warp = tid >> 5, lane = tid & 31;
    const int g = lane >> 2, t = lane & 3;
    const int rowg = warp & 3, colg = warp >> 2;

    for (int i = tid; i < 64 * 64; i += 256) {
        int k = i >> 6, n = i & 63;
        W1t[n * 68 + k] = rna_f(w1[i]);
        W2t[n * 68 + k] = rna_f(w2[i]);
    }
    if (tid < 64) { bs0[tid] = b0[tid]; bs1[tid] = b1[tid]; bs2[tid] = b2[tid]; }
    __syncthreads();

    const float* gP = (const float*)g_P4;
    const float* gQ = (const float*)g_Q4;
    float* g_new = (float*)g_new_states4;

    for (int tile = blockIdx.x; tile < N_ETILES; tile += gridDim.x) {
        const int e0 = tile * ETILE;
        if (tid < 128) sdst[tid]       = edge_dst[e0 + tid];
        else           ssrc[tid - 128] = edge_src[e0 + tid - 128];
        __syncthreads();

        // A0 = rna(relu(P[dst] + Q[src] + b0))
        for (int i = tid; i < 128 * 16; i += 256) {
            const int r = i >> 4, q = i & 15;
            const float4 p = *(const float4*)(gP + (size_t)sdst[r] * 64 + q * 4);
            const float4 s = *(const float4*)(gQ + (size_t)ssrc[r] * 64 + q * 4);
            float4 o;
            o.x = rna_f(fmaxf(p.x + s.x + bs0[q * 4 + 0], 0.f));
            o.y = rna_f(fmaxf(p.y + s.y + bs0[q * 4 + 1], 0.f));
            o.z = rna_f(fmaxf(p.z + s.z + bs0[q * 4 + 2], 0.f));
            o.w = rna_f(fmaxf(p.w + s.w + bs0[q * 4 + 3], 0.f));
            *(float4*)(Xs + (size_t)r * 68 + q * 4) = o;
        }
        __syncthreads();

        layer32<true >(Xs, W1t, bs1, Ys, rowg, colg, g, t);   // L1: Xs -> Ys
        __syncthreads();
        layer32<false>(Ys, W2t, bs2, Xs, rowg, colg, g, t);   // L2: Ys -> Xs
        __syncthreads();

        // scatter messages
        for (int i = tid; i < 128 * 16; i += 256) {
            const int r = i >> 4, q = i & 15;
            const float4 v = *(const float4*)(Xs + (size_t)r * 68 + q * 4);
            float* p = g_new + (size_t)sdst[r] * 64 + q * 4;
            asm volatile("red.global.add.v4.f32 [%0], {%1,%2,%3,%4};"
                         :: "l"(p), "f"(v.x), "f"(v.y), "f"(v.z), "f"(v.w) : "memory");
        }
        __syncthreads();
    }
}

// ====================== readout kernel (unchanged from R1) ======================
template<int KDIM, int NT, int ASTRIDE, int WSTRIDE, int YSTRIDE, bool ROUND>
__device__ __forceinline__ void mlp_layer(
    const float* __restrict__ As, const float* __restrict__ Wt,
    const float* __restrict__ bias, float* __restrict__ Ys,
    int warp, int gg, int t)
{
    float c[NT][4];
#pragma unroll
    for (int nt = 0; nt < NT; nt++) {
        float v0 = bias[nt * 8 + 2 * t];
        float v1 = bias[nt * 8 + 2 * t + 1];
        c[nt][0] = v0; c[nt][1] = v1; c[nt][2] = v0; c[nt][3] = v1;
    }
    const unsigned* Au = (const unsigned*)As;
    const unsigned* Wu = (const unsigned*)Wt;
    const int row0 = warp * 16 + gg;
#pragma unroll
    for (int kt = 0; kt < KDIM / 8; kt++) {
        const int kb = kt * 8;
        unsigned a[4];
        a[0] = Au[(size_t)row0       * ASTRIDE + kb + t];
        a[1] = Au[(size_t)(row0 + 8) * ASTRIDE + kb + t];
        a[2] = Au[(size_t)row0       * ASTRIDE + kb + t + 4];
        a[3] = Au[(size_t)(row0 + 8) * ASTRIDE + kb + t + 4];
#pragma unroll
        for (int nt = 0; nt < NT; nt++) {
            unsigned b[2];
            b[0] = Wu[(nt * 8 + gg) * WSTRIDE + kb + t];
            b[1] = Wu[(nt * 8 + gg) * WSTRIDE + kb + t + 4];
            mma8(c[nt], a, b);
        }
    }
#pragma unroll
    for (int nt = 0; nt < NT; nt++) {
        const int col = nt * 8 + 2 * t;
        float v0 = fmaxf(c[nt][0], 0.f), v1 = fmaxf(c[nt][1], 0.f);
        float v2 = fmaxf(c[nt][2], 0.f), v3 = fmaxf(c[nt][3], 0.f);
        if (ROUND) { v0 = rna_f(v0); v1 = rna_f(v1); v2 = rna_f(v2); v3 = rna_f(v3); }
        Ys[(size_t)row0       * YSTRIDE + col]     = v0;
        Ys[(size_t)row0       * YSTRIDE + col + 1] = v1;
        Ys[(size_t)(row0 + 8) * YSTRIDE + col]     = v2;
        Ys[(size_t)(row0 + 8) * YSTRIDE + col + 1] = v3;
    }
}

#define R_XS    0
#define R_Y0    (R_XS + 128*68)
#define R_Y1    (R_Y0 + 128*68)
#define R_W1T   (R_Y1 + 128*68)
#define R_W2T   (R_W1T + 64*68)
#define R_W3T   (R_W2T + 64*68)
#define R_B1    (R_W3T + 16*68)
#define R_B2    (R_B1 + 64)
#define R_B3    (R_B2 + 64)
#define R_O     (R_B3 + 16)
#define R_SMEM_FLOATS (R_O + 128*16)
#define R_SMEM_BYTES  (R_SMEM_FLOATS * 4)

__global__ void __launch_bounds__(256, 1) readout_kernel(
    const float* __restrict__ fc1w, const float* __restrict__ fc1b,
    const float* __restrict__ fc2w, const float* __restrict__ fc2b,
    const float* __restrict__ outw, const float* __restrict__ outb,
    float* __restrict__ out)
{
    extern __shared__ float sm[];
    float* Xs  = sm + R_XS;
    float* Y0  = sm + R_Y0;
    float* Y1  = sm + R_Y1;
    float* W1t = sm + R_W1T;
    float* W2t = sm + R_W2T;
    float* W3t = sm + R_W3T;
    float* bsa = sm + R_B1;
    float* bsb = sm + R_B2;
    float* bsc = sm + R_B3;
    float* O   = sm + R_O;

    const int tid  = threadIdx.x;
    const int warp = tid >> 5, lane = tid & 31;
    const int gg = lane >> 2, t = lane & 3;

    for (int i = tid; i < 64 * 64; i += 256) {
        int k = i >> 6, n = i & 63;
        W1t[n * 68 + k] = rna_f(fc1w[i]);
        W2t[n * 68 + k] = rna_f(fc2w[i]);
    }
    for (int i = tid; i < 64 * 16; i += 256) {
        int k = i >> 4, n = i & 15;
        W3t[n * 68 + k] = rna_f(outw[i]);
    }
    if (tid < 64) { bsa[tid] = fc1b[tid]; bsb[tid] = fc2b[tid]; }
    if (tid < 16) bsc[tid] = outb[tid];
    __syncthreads();

    const int tile = blockIdx.x;
    const float* g_new = (const float*)g_new_states4;

    for (int i = tid; i < 128 * 16; i += 256) {
        const int rr = i >> 4, q = i & 15;
        const float4 v = *(const float4*)(g_new + ((size_t)tile * 128 + rr) * 64 + q * 4);
        float4 o;
        o.x = rna_f(v.x); o.y = rna_f(v.y); o.z = rna_f(v.z); o.w = rna_f(v.w);
        *(float4*)(Xs + (size_t)rr * 68 + q * 4) = o;
    }
    __syncthreads();

    mlp_layer<64, 8, 68, 68, 68, true >(Xs, W1t, bsa, Y0, warp, gg, t);
    __syncthreads();
    mlp_layer<64, 8, 68, 68, 68, true >(Y0, W2t, bsb, Y1, warp, gg, t);
    __syncthreads();
    mlp_layer<64, 2, 68, 68, 16, false>(Y1, W3t, bsc, O, warp, gg, t);
    __syncthreads();

    if (tid < 64) {
        const int mol = tid >> 4, col = tid & 15;
        float s = 0.f;
#pragma unroll
        for (int rr = 0; rr < 32; rr++) s += O[(mol * 32 + rr) * 16 + col];
        out[((size_t)tile * 4 + mol) * 16 + col] = s;
    }
}

extern "C" void kernel_launch(void* const* d_in, const int* in_sizes, int n_in,
                              void* d_out, int out_size) {
    const float* atom_states = (const float*)d_in[0];
    const int*   edge_src    = (const int*)d_in[1];
    const int*   edge_dst    = (const int*)d_in[2];
    const float* ms0w = (const float*)d_in[4];  const float* ms0b = (const float*)d_in[5];
    const float* ms1w = (const float*)d_in[6];  const float* ms1b = (const float*)d_in[7];
    const float* ms2w = (const float*)d_in[8];  const float* ms2b = (const float*)d_in[9];
    const float* fc1w = (const float*)d_in[10]; const float* fc1b = (const float*)d_in[11];
    const float* fc2w = (const float*)d_in[12]; const float* fc2b = (const float*)d_in[13];
    const float* outw = (const float*)d_in[14]; const float* outb = (const float*)d_in[15];
    float* out = (float*)d_out;

    cudaFuncSetAttribute(pq_kernel, cudaFuncAttributeMaxDynamicSharedMemorySize, PQ_SMEM_BYTES);
    cudaFuncSetAttribute(edge_kernel, cudaFuncAttributeMaxDynamicSharedMemorySize, E_SMEM_BYTES);
    cudaFuncSetAttribute(readout_kernel, cudaFuncAttributeMaxDynamicSharedMemorySize, R_SMEM_BYTES);

    int sms = 148;
    cudaDeviceGetAttribute(&sms, cudaDevAttrMultiProcessorCount, 0);

    pq_kernel<<<N_ATILES, 256, PQ_SMEM_BYTES>>>(atom_states, ms0w);
    edge_kernel<<<2 * sms, 256, E_SMEM_BYTES>>>(edge_src, edge_dst,
                                                ms0b, ms1w, ms1b, ms2w, ms2b);
    readout_kernel<<<N_ATILES, 256, R_SMEM_BYTES>>>(fc1w, fc1b, fc2w, fc2b,
                                                    outw, outb, out);
}